// round 1
// baseline (speedup 1.0000x reference)
#include <cuda_runtime.h>
#include <cstdint>

#define NB 2
#define NS 2048
#define ND 768
#define NH 12
#define NHD 64
#define NFF 3072
#define NM (NB*NS)   // 4096 rows

// ---------------- scratch (static device allocations, allowed) ----------------
__device__ float g_q[NB*NH*NS*NHD];
__device__ float g_k[NB*NH*NS*NHD];
__device__ float g_v[NB*NH*NS*NHD];
__device__ float g_attn[NM*ND];
__device__ float g_tmp[NM*ND];
__device__ float g_x1[NM*ND];
__device__ float g_ff[(size_t)NM*NFF];

// ---------------------------------------------------------------------------
// Tiled SGEMM: C[m,n] = sum_k A[m,k] * W[n,k] + bias[n]  (+relu / +residual)
// 64x64 block tile, 256 threads, 4x4 per thread, K-tile 32.
// headsplit=1 stores C into (B,H,S,HD) layout (n -> h,hd ; m -> b,s).
// ---------------------------------------------------------------------------
__global__ __launch_bounds__(256) void gemm_kernel(
    const float* __restrict__ A, const float* __restrict__ W,
    const float* __restrict__ bias, const float* __restrict__ res,
    float* __restrict__ C, int M, int N, int K, int relu, int headsplit)
{
    __shared__ __align__(16) float As[32][68];
    __shared__ __align__(16) float Bs[32][68];
    const int tid = threadIdx.x;
    const int ty = tid >> 4, tx = tid & 15;
    const int m0 = blockIdx.y << 6, n0 = blockIdx.x << 6;

    float acc[4][4] = {};

    for (int k0 = 0; k0 < K; k0 += 32) {
        #pragma unroll
        for (int c = 0; c < 2; c++) {
            int idx = tid + (c << 8);          // 0..511
            int row = idx >> 3;                 // 0..63
            int col = (idx & 7) << 2;           // 0..28 step 4
            float4 va = *reinterpret_cast<const float4*>(A + (size_t)(m0+row)*K + k0 + col);
            As[col+0][row] = va.x; As[col+1][row] = va.y;
            As[col+2][row] = va.z; As[col+3][row] = va.w;
            float4 vb = *reinterpret_cast<const float4*>(W + (size_t)(n0+row)*K + k0 + col);
            Bs[col+0][row] = vb.x; Bs[col+1][row] = vb.y;
            Bs[col+2][row] = vb.z; Bs[col+3][row] = vb.w;
        }
        __syncthreads();
        #pragma unroll
        for (int kk = 0; kk < 32; kk++) {
            float4 a4 = *reinterpret_cast<const float4*>(&As[kk][ty << 2]);
            float4 b4 = *reinterpret_cast<const float4*>(&Bs[kk][tx << 2]);
            float av[4] = {a4.x, a4.y, a4.z, a4.w};
            float bv[4] = {b4.x, b4.y, b4.z, b4.w};
            #pragma unroll
            for (int i = 0; i < 4; i++)
                #pragma unroll
                for (int j = 0; j < 4; j++)
                    acc[i][j] = fmaf(av[i], bv[j], acc[i][j]);
        }
        __syncthreads();
    }

    #pragma unroll
    for (int i = 0; i < 4; i++) {
        int m = m0 + (ty << 2) + i;
        #pragma unroll
        for (int j = 0; j < 4; j++) {
            int n = n0 + (tx << 2) + j;
            float v = acc[i][j] + bias[n];
            if (relu) v = fmaxf(v, 0.0f);
            if (res)  v += res[(size_t)m * N + n];
            if (headsplit) {
                int h = n >> 6, hd = n & 63;
                int b = m >> 11, s = m & (NS - 1);
                C[(((size_t)(b * NH + h)) * NS + s) * NHD + hd] = v;
            } else {
                C[(size_t)m * N + n] = v;
            }
        }
    }
}

// ---------------------------------------------------------------------------
// Flash attention, fp32. 64 queries x 64-key tiles, 256 threads, 4x4/thread.
// ALiBi + causal mask computed analytically. P tile reuses the K smem buffer.
// Q/K stored transposed [d][row] in smem; V natural [row][d].
// ---------------------------------------------------------------------------
__global__ __launch_bounds__(256) void attn_kernel(
    const float* __restrict__ Q, const float* __restrict__ K,
    const float* __restrict__ V, float* __restrict__ O)
{
    extern __shared__ __align__(16) float sm[];
    float* Qs = sm;                 // [64][68]  (transposed: [d][q])
    float* Ks = sm + 64 * 68;       // [64][68]  (transposed: [d][k]), reused as P[k][q]
    float* Vs = sm + 2 * 64 * 68;   // [64][68]  (natural:   [k][d])

    const int tid = threadIdx.x;
    const int ty = tid >> 4, tx = tid & 15;
    const int q0 = blockIdx.x << 6;
    const int bh = blockIdx.y;
    const int h  = bh % NH;
    const int b  = bh / NH;
    const size_t base = (size_t)bh * NS * NHD;
    const float slope = exp2f(-(8.0f / NH) * (float)(h + 1));

    // load Q tile transposed
    #pragma unroll
    for (int c = 0; c < 4; c++) {
        int idx = tid + (c << 8);     // 0..1023
        int row = idx >> 4;           // 0..63
        int col = (idx & 15) << 2;    // 0..60 step 4
        float4 v = *reinterpret_cast<const float4*>(Q + base + (size_t)(q0 + row) * NHD + col);
        Qs[(col + 0) * 68 + row] = v.x; Qs[(col + 1) * 68 + row] = v.y;
        Qs[(col + 2) * 68 + row] = v.z; Qs[(col + 3) * 68 + row] = v.w;
    }

    float m_r[4], l_r[4];
    float acc_o[4][4] = {};
    #pragma unroll
    for (int i = 0; i < 4; i++) { m_r[i] = -1e30f; l_r[i] = 0.0f; }

    const int nt = (q0 >> 6) + 1;   // causal: key tiles 0..q0/64
    for (int t = 0; t < nt; t++) {
        const int k0 = t << 6;
        __syncthreads();   // prior O-GEMM reads of Ks/Vs done (also orders Qs stores on t=0)

        #pragma unroll
        for (int c = 0; c < 4; c++) {
            int idx = tid + (c << 8);
            int row = idx >> 4;
            int col = (idx & 15) << 2;
            float4 kv = *reinterpret_cast<const float4*>(K + base + (size_t)(k0 + row) * NHD + col);
            Ks[(col + 0) * 68 + row] = kv.x; Ks[(col + 1) * 68 + row] = kv.y;
            Ks[(col + 2) * 68 + row] = kv.z; Ks[(col + 3) * 68 + row] = kv.w;
            float4 vv = *reinterpret_cast<const float4*>(V + base + (size_t)(k0 + row) * NHD + col);
            *reinterpret_cast<float4*>(&Vs[row * 68 + col]) = vv;
        }
        __syncthreads();

        // S = Q K^T
        float s_acc[4][4] = {};
        #pragma unroll
        for (int kk = 0; kk < 64; kk++) {
            float4 a4 = *reinterpret_cast<const float4*>(&Qs[kk * 68 + (ty << 2)]);
            float4 b4 = *reinterpret_cast<const float4*>(&Ks[kk * 68 + (tx << 2)]);
            float av[4] = {a4.x, a4.y, a4.z, a4.w};
            float bv[4] = {b4.x, b4.y, b4.z, b4.w};
            #pragma unroll
            for (int i = 0; i < 4; i++)
                #pragma unroll
                for (int j = 0; j < 4; j++)
                    s_acc[i][j] = fmaf(av[i], bv[j], s_acc[i][j]);
        }

        // scale + ALiBi + causal mask + online softmax
        float p[4][4];
        #pragma unroll
        for (int i = 0; i < 4; i++) {
            int q = q0 + (ty << 2) + i;
            float rowmax = -1e30f;
            #pragma unroll
            for (int j = 0; j < 4; j++) {
                int kc = k0 + (tx << 2) + j;
                float s = fmaf(s_acc[i][j], 0.125f, slope * (float)(kc - q));
                if (kc > q) s = -1e30f;
                s_acc[i][j] = s;
                rowmax = fmaxf(rowmax, s);
            }
            #pragma unroll
            for (int off = 1; off < 16; off <<= 1)
                rowmax = fmaxf(rowmax, __shfl_xor_sync(0xffffffffu, rowmax, off));
            float mnew = fmaxf(m_r[i], rowmax);
            float alpha = __expf(m_r[i] - mnew);
            float rsum = 0.0f;
            #pragma unroll
            for (int j = 0; j < 4; j++) {
                p[i][j] = __expf(s_acc[i][j] - mnew);
                rsum += p[i][j];
            }
            #pragma unroll
            for (int off = 1; off < 16; off <<= 1)
                rsum += __shfl_xor_sync(0xffffffffu, rsum, off);
            l_r[i] = l_r[i] * alpha + rsum;
            #pragma unroll
            for (int j = 0; j < 4; j++) acc_o[i][j] *= alpha;
            m_r[i] = mnew;
        }

        __syncthreads();   // everyone done reading Ks
        #pragma unroll
        for (int i = 0; i < 4; i++)
            #pragma unroll
            for (int j = 0; j < 4; j++)
                Ks[((tx << 2) + j) * 68 + (ty << 2) + i] = p[i][j];   // P[k][q]
        __syncthreads();

        // O += P V
        #pragma unroll
        for (int kk = 0; kk < 64; kk++) {
            float4 a4 = *reinterpret_cast<const float4*>(&Ks[kk * 68 + (ty << 2)]);
            float4 b4 = *reinterpret_cast<const float4*>(&Vs[kk * 68 + (tx << 2)]);
            float av[4] = {a4.x, a4.y, a4.z, a4.w};
            float bv[4] = {b4.x, b4.y, b4.z, b4.w};
            #pragma unroll
            for (int i = 0; i < 4; i++)
                #pragma unroll
                for (int j = 0; j < 4; j++)
                    acc_o[i][j] = fmaf(av[i], bv[j], acc_o[i][j]);
        }
    }

    // write (B,S,D)
    #pragma unroll
    for (int i = 0; i < 4; i++) {
        int q = q0 + (ty << 2) + i;
        float inv_l = 1.0f / l_r[i];
        float4 o4;
        o4.x = acc_o[i][0] * inv_l; o4.y = acc_o[i][1] * inv_l;
        o4.z = acc_o[i][2] * inv_l; o4.w = acc_o[i][3] * inv_l;
        *reinterpret_cast<float4*>(O + ((size_t)(b * NS + q)) * ND + h * NHD + (tx << 2)) = o4;
    }
}

// ---------------------------------------------------------------------------
// LayerNorm over last dim (768). One block per row, two-pass (matches ref).
// ---------------------------------------------------------------------------
__global__ __launch_bounds__(256) void ln_kernel(
    const float* __restrict__ X, const float* __restrict__ g,
    const float* __restrict__ be, float* __restrict__ Y)
{
    __shared__ float red[256];
    const int row = blockIdx.x;
    const int tid = threadIdx.x;
    const float* x = X + (size_t)row * ND;

    float s = 0.0f;
    for (int i = tid; i < ND; i += 256) s += x[i];
    red[tid] = s; __syncthreads();
    for (int off = 128; off > 0; off >>= 1) {
        if (tid < off) red[tid] += red[tid + off];
        __syncthreads();
    }
    float mu = red[0] * (1.0f / ND);
    __syncthreads();

    float vs = 0.0f;
    for (int i = tid; i < ND; i += 256) { float d = x[i] - mu; vs = fmaf(d, d, vs); }
    red[tid] = vs; __syncthreads();
    for (int off = 128; off > 0; off >>= 1) {
        if (tid < off) red[tid] += red[tid + off];
        __syncthreads();
    }
    float rstd = rsqrtf(red[0] * (1.0f / ND) + 1e-5f);

    for (int i = tid; i < ND; i += 256)
        Y[(size_t)row * ND + i] = (x[i] - mu) * rstd * g[i] + be[i];
}

// ---------------------------------------------------------------------------
extern "C" void kernel_launch(void* const* d_in, const int* in_sizes, int n_in,
                              void* d_out, int out_size)
{
    const float* x   = (const float*)d_in[0];
    // d_in[1] = mask, d_in[2] = alibi_bias  (computed analytically, not read)
    const float* wq  = (const float*)d_in[3];
    const float* bq  = (const float*)d_in[4];
    const float* wk  = (const float*)d_in[5];
    const float* bk  = (const float*)d_in[6];
    const float* wv  = (const float*)d_in[7];
    const float* bv  = (const float*)d_in[8];
    const float* wo  = (const float*)d_in[9];
    const float* bo  = (const float*)d_in[10];
    const float* w1  = (const float*)d_in[11];
    const float* b1  = (const float*)d_in[12];
    const float* w2  = (const float*)d_in[13];
    const float* b2  = (const float*)d_in[14];
    const float* g1  = (const float*)d_in[15];
    const float* be1 = (const float*)d_in[16];
    const float* g2  = (const float*)d_in[17];
    const float* be2 = (const float*)d_in[18];
    float* out = (float*)d_out;

    float *q_p, *k_p, *v_p, *attn_p, *tmp_p, *x1_p, *ff_p;
    cudaGetSymbolAddress((void**)&q_p,   g_q);
    cudaGetSymbolAddress((void**)&k_p,   g_k);
    cudaGetSymbolAddress((void**)&v_p,   g_v);
    cudaGetSymbolAddress((void**)&attn_p,g_attn);
    cudaGetSymbolAddress((void**)&tmp_p, g_tmp);
    cudaGetSymbolAddress((void**)&x1_p,  g_x1);
    cudaGetSymbolAddress((void**)&ff_p,  g_ff);

    const int attn_smem = 3 * 64 * 68 * (int)sizeof(float);   // 52224 B
    cudaFuncSetAttribute(attn_kernel, cudaFuncAttributeMaxDynamicSharedMemorySize, attn_smem);

    dim3 blk(256);

    // QKV projections -> (B,H,S,HD)
    gemm_kernel<<<dim3(ND/64,  NM/64), blk>>>(x, wq, bq, nullptr, q_p, NM, ND, ND, 0, 1);
    gemm_kernel<<<dim3(ND/64,  NM/64), blk>>>(x, wk, bk, nullptr, k_p, NM, ND, ND, 0, 1);
    gemm_kernel<<<dim3(ND/64,  NM/64), blk>>>(x, wv, bv, nullptr, v_p, NM, ND, ND, 0, 1);

    // attention -> (B,S,D)
    attn_kernel<<<dim3(NS/64, NB*NH), blk, attn_smem>>>(q_p, k_p, v_p, attn_p);

    // O projection + residual, then LN1
    gemm_kernel<<<dim3(ND/64,  NM/64), blk>>>(attn_p, wo, bo, x, tmp_p, NM, ND, ND, 0, 0);
    ln_kernel<<<NM, 256>>>(tmp_p, g1, be1, x1_p);

    // FFN
    gemm_kernel<<<dim3(NFF/64, NM/64), blk>>>(x1_p, w1, b1, nullptr, ff_p, NM, NFF, ND, 1, 0);
    gemm_kernel<<<dim3(ND/64,  NM/64), blk>>>(ff_p, w2, b2, x1_p, tmp_p, NM, ND, NFF, 0, 0);
    ln_kernel<<<NM, 256>>>(tmp_p, g2, be2, out);
}

// round 2
// speedup vs baseline: 1.0031x; 1.0031x over previous
#include <cuda_runtime.h>
#include <cstdint>

#define NB 2
#define NS 2048
#define ND 768
#define NH 12
#define NHD 64
#define NFF 3072
#define NM (NB*NS)   // 4096 rows

// ---------------- scratch (static device allocations, allowed) ----------------
__device__ float g_q[NB*NH*NS*NHD];
__device__ float g_k[NB*NH*NS*NHD];
__device__ float g_v[NB*NH*NS*NHD];
__device__ float g_attn[NM*ND];
__device__ float g_tmp[NM*ND];
__device__ float g_x1[NM*ND];
__device__ float g_ff[(size_t)NM*NFF];

// ---------------------------------------------------------------------------
// Tiled SGEMM: C[m,n] = sum_k A[m,k] * W[n,k] + bias[n]  (+relu / +residual)
// 64x64 block tile, 256 threads, 4x4 per thread, K-tile 32.
// headsplit=1 stores C into (B,H,S,HD) layout (n -> h,hd ; m -> b,s).
// ---------------------------------------------------------------------------
__global__ __launch_bounds__(256) void gemm_kernel(
    const float* __restrict__ A, const float* __restrict__ W,
    const float* __restrict__ bias, const float* __restrict__ res,
    float* __restrict__ C, int M, int N, int K, int relu, int headsplit)
{
    __shared__ __align__(16) float As[32][68];
    __shared__ __align__(16) float Bs[32][68];
    const int tid = threadIdx.x;
    const int ty = tid >> 4, tx = tid & 15;
    const int m0 = blockIdx.y << 6, n0 = blockIdx.x << 6;

    float acc[4][4] = {};

    for (int k0 = 0; k0 < K; k0 += 32) {
        #pragma unroll
        for (int c = 0; c < 2; c++) {
            int idx = tid + (c << 8);          // 0..511
            int row = idx >> 3;                 // 0..63
            int col = (idx & 7) << 2;           // 0..28 step 4
            float4 va = *reinterpret_cast<const float4*>(A + (size_t)(m0+row)*K + k0 + col);
            As[col+0][row] = va.x; As[col+1][row] = va.y;
            As[col+2][row] = va.z; As[col+3][row] = va.w;
            float4 vb = *reinterpret_cast<const float4*>(W + (size_t)(n0+row)*K + k0 + col);
            Bs[col+0][row] = vb.x; Bs[col+1][row] = vb.y;
            Bs[col+2][row] = vb.z; Bs[col+3][row] = vb.w;
        }
        __syncthreads();
        #pragma unroll
        for (int kk = 0; kk < 32; kk++) {
            float4 a4 = *reinterpret_cast<const float4*>(&As[kk][ty << 2]);
            float4 b4 = *reinterpret_cast<const float4*>(&Bs[kk][tx << 2]);
            float av[4] = {a4.x, a4.y, a4.z, a4.w};
            float bv[4] = {b4.x, b4.y, b4.z, b4.w};
            #pragma unroll
            for (int i = 0; i < 4; i++)
                #pragma unroll
                for (int j = 0; j < 4; j++)
                    acc[i][j] = fmaf(av[i], bv[j], acc[i][j]);
        }
        __syncthreads();
    }

    #pragma unroll
    for (int i = 0; i < 4; i++) {
        int m = m0 + (ty << 2) + i;
        #pragma unroll
        for (int j = 0; j < 4; j++) {
            int n = n0 + (tx << 2) + j;
            float v = acc[i][j] + bias[n];
            if (relu) v = fmaxf(v, 0.0f);
            if (res)  v += res[(size_t)m * N + n];
            if (headsplit) {
                int h = n >> 6, hd = n & 63;
                int b = m >> 11, s = m & (NS - 1);
                C[(((size_t)(b * NH + h)) * NS + s) * NHD + hd] = v;
            } else {
                C[(size_t)m * N + n] = v;
            }
        }
    }
}

// ---------------------------------------------------------------------------
// Flash attention, fp32. 64 queries x 64-key tiles, 256 threads, 4x4/thread.
// ALiBi + causal mask computed analytically. P tile reuses the K smem buffer.
// Q/K stored transposed [d][row] in smem; V natural [row][d].
// ---------------------------------------------------------------------------
__global__ __launch_bounds__(256) void attn_kernel(
    const float* __restrict__ Q, const float* __restrict__ K,
    const float* __restrict__ V, float* __restrict__ O)
{
    extern __shared__ __align__(16) float sm[];
    float* Qs = sm;                 // [64][68]  (transposed: [d][q])
    float* Ks = sm + 64 * 68;       // [64][68]  (transposed: [d][k]), reused as P[k][q]
    float* Vs = sm + 2 * 64 * 68;   // [64][68]  (natural:   [k][d])

    const int tid = threadIdx.x;
    const int ty = tid >> 4, tx = tid & 15;
    const int q0 = blockIdx.x << 6;
    const int bh = blockIdx.y;
    const int h  = bh % NH;
    const int b  = bh / NH;
    const size_t base = (size_t)bh * NS * NHD;
    const float slope = exp2f(-(8.0f / NH) * (float)(h + 1));

    // load Q tile transposed
    #pragma unroll
    for (int c = 0; c < 4; c++) {
        int idx = tid + (c << 8);     // 0..1023
        int row = idx >> 4;           // 0..63
        int col = (idx & 15) << 2;    // 0..60 step 4
        float4 v = *reinterpret_cast<const float4*>(Q + base + (size_t)(q0 + row) * NHD + col);
        Qs[(col + 0) * 68 + row] = v.x; Qs[(col + 1) * 68 + row] = v.y;
        Qs[(col + 2) * 68 + row] = v.z; Qs[(col + 3) * 68 + row] = v.w;
    }

    float m_r[4], l_r[4];
    float acc_o[4][4] = {};
    #pragma unroll
    for (int i = 0; i < 4; i++) { m_r[i] = -1e30f; l_r[i] = 0.0f; }

    const int nt = (q0 >> 6) + 1;   // causal: key tiles 0..q0/64
    for (int t = 0; t < nt; t++) {
        const int k0 = t << 6;
        __syncthreads();   // prior O-GEMM reads of Ks/Vs done (also orders Qs stores on t=0)

        #pragma unroll
        for (int c = 0; c < 4; c++) {
            int idx = tid + (c << 8);
            int row = idx >> 4;
            int col = (idx & 15) << 2;
            float4 kv = *reinterpret_cast<const float4*>(K + base + (size_t)(k0 + row) * NHD + col);
            Ks[(col + 0) * 68 + row] = kv.x; Ks[(col + 1) * 68 + row] = kv.y;
            Ks[(col + 2) * 68 + row] = kv.z; Ks[(col + 3) * 68 + row] = kv.w;
            float4 vv = *reinterpret_cast<const float4*>(V + base + (size_t)(k0 + row) * NHD + col);
            *reinterpret_cast<float4*>(&Vs[row * 68 + col]) = vv;
        }
        __syncthreads();

        // S = Q K^T
        float s_acc[4][4] = {};
        #pragma unroll
        for (int kk = 0; kk < 64; kk++) {
            float4 a4 = *reinterpret_cast<const float4*>(&Qs[kk * 68 + (ty << 2)]);
            float4 b4 = *reinterpret_cast<const float4*>(&Ks[kk * 68 + (tx << 2)]);
            float av[4] = {a4.x, a4.y, a4.z, a4.w};
            float bv[4] = {b4.x, b4.y, b4.z, b4.w};
            #pragma unroll
            for (int i = 0; i < 4; i++)
                #pragma unroll
                for (int j = 0; j < 4; j++)
                    s_acc[i][j] = fmaf(av[i], bv[j], s_acc[i][j]);
        }

        // scale + ALiBi + causal mask + online softmax
        float p[4][4];
        #pragma unroll
        for (int i = 0; i < 4; i++) {
            int q = q0 + (ty << 2) + i;
            float rowmax = -1e30f;
            #pragma unroll
            for (int j = 0; j < 4; j++) {
                int kc = k0 + (tx << 2) + j;
                float s = fmaf(s_acc[i][j], 0.125f, slope * (float)(kc - q));
                if (kc > q) s = -1e30f;
                s_acc[i][j] = s;
                rowmax = fmaxf(rowmax, s);
            }
            #pragma unroll
            for (int off = 1; off < 16; off <<= 1)
                rowmax = fmaxf(rowmax, __shfl_xor_sync(0xffffffffu, rowmax, off));
            float mnew = fmaxf(m_r[i], rowmax);
            float alpha = __expf(m_r[i] - mnew);
            float rsum = 0.0f;
            #pragma unroll
            for (int j = 0; j < 4; j++) {
                p[i][j] = __expf(s_acc[i][j] - mnew);
                rsum += p[i][j];
            }
            #pragma unroll
            for (int off = 1; off < 16; off <<= 1)
                rsum += __shfl_xor_sync(0xffffffffu, rsum, off);
            l_r[i] = l_r[i] * alpha + rsum;
            #pragma unroll
            for (int j = 0; j < 4; j++) acc_o[i][j] *= alpha;
            m_r[i] = mnew;
        }

        __syncthreads();   // everyone done reading Ks
        #pragma unroll
        for (int i = 0; i < 4; i++)
            #pragma unroll
            for (int j = 0; j < 4; j++)
                Ks[((tx << 2) + j) * 68 + (ty << 2) + i] = p[i][j];   // P[k][q]
        __syncthreads();

        // O += P V
        #pragma unroll
        for (int kk = 0; kk < 64; kk++) {
            float4 a4 = *reinterpret_cast<const float4*>(&Ks[kk * 68 + (ty << 2)]);
            float4 b4 = *reinterpret_cast<const float4*>(&Vs[kk * 68 + (tx << 2)]);
            float av[4] = {a4.x, a4.y, a4.z, a4.w};
            float bv[4] = {b4.x, b4.y, b4.z, b4.w};
            #pragma unroll
            for (int i = 0; i < 4; i++)
                #pragma unroll
                for (int j = 0; j < 4; j++)
                    acc_o[i][j] = fmaf(av[i], bv[j], acc_o[i][j]);
        }
    }

    // write (B,S,D)
    #pragma unroll
    for (int i = 0; i < 4; i++) {
        int q = q0 + (ty << 2) + i;
        float inv_l = 1.0f / l_r[i];
        float4 o4;
        o4.x = acc_o[i][0] * inv_l; o4.y = acc_o[i][1] * inv_l;
        o4.z = acc_o[i][2] * inv_l; o4.w = acc_o[i][3] * inv_l;
        *reinterpret_cast<float4*>(O + ((size_t)(b * NS + q)) * ND + h * NHD + (tx << 2)) = o4;
    }
}

// ---------------------------------------------------------------------------
// LayerNorm over last dim (768). One block per row, two-pass (matches ref).
// ---------------------------------------------------------------------------
__global__ __launch_bounds__(256) void ln_kernel(
    const float* __restrict__ X, const float* __restrict__ g,
    const float* __restrict__ be, float* __restrict__ Y)
{
    __shared__ float red[256];
    const int row = blockIdx.x;
    const int tid = threadIdx.x;
    const float* x = X + (size_t)row * ND;

    float s = 0.0f;
    for (int i = tid; i < ND; i += 256) s += x[i];
    red[tid] = s; __syncthreads();
    for (int off = 128; off > 0; off >>= 1) {
        if (tid < off) red[tid] += red[tid + off];
        __syncthreads();
    }
    float mu = red[0] * (1.0f / ND);
    __syncthreads();

    float vs = 0.0f;
    for (int i = tid; i < ND; i += 256) { float d = x[i] - mu; vs = fmaf(d, d, vs); }
    red[tid] = vs; __syncthreads();
    for (int off = 128; off > 0; off >>= 1) {
        if (tid < off) red[tid] += red[tid + off];
        __syncthreads();
    }
    float rstd = rsqrtf(red[0] * (1.0f / ND) + 1e-5f);

    for (int i = tid; i < ND; i += 256)
        Y[(size_t)row * ND + i] = (x[i] - mu) * rstd * g[i] + be[i];
}

// ---------------------------------------------------------------------------
extern "C" void kernel_launch(void* const* d_in, const int* in_sizes, int n_in,
                              void* d_out, int out_size)
{
    const float* x   = (const float*)d_in[0];
    // d_in[1] = mask, d_in[2] = alibi_bias  (computed analytically, not read)
    const float* wq  = (const float*)d_in[3];
    const float* bq  = (const float*)d_in[4];
    const float* wk  = (const float*)d_in[5];
    const float* bk  = (const float*)d_in[6];
    const float* wv  = (const float*)d_in[7];
    const float* bv  = (const float*)d_in[8];
    const float* wo  = (const float*)d_in[9];
    const float* bo  = (const float*)d_in[10];
    const float* w1  = (const float*)d_in[11];
    const float* b1  = (const float*)d_in[12];
    const float* w2  = (const float*)d_in[13];
    const float* b2  = (const float*)d_in[14];
    const float* g1  = (const float*)d_in[15];
    const float* be1 = (const float*)d_in[16];
    const float* g2  = (const float*)d_in[17];
    const float* be2 = (const float*)d_in[18];
    float* out = (float*)d_out;

    float *q_p, *k_p, *v_p, *attn_p, *tmp_p, *x1_p, *ff_p;
    cudaGetSymbolAddress((void**)&q_p,   g_q);
    cudaGetSymbolAddress((void**)&k_p,   g_k);
    cudaGetSymbolAddress((void**)&v_p,   g_v);
    cudaGetSymbolAddress((void**)&attn_p,g_attn);
    cudaGetSymbolAddress((void**)&tmp_p, g_tmp);
    cudaGetSymbolAddress((void**)&x1_p,  g_x1);
    cudaGetSymbolAddress((void**)&ff_p,  g_ff);

    const int attn_smem = 3 * 64 * 68 * (int)sizeof(float);   // 52224 B
    cudaFuncSetAttribute(attn_kernel, cudaFuncAttributeMaxDynamicSharedMemorySize, attn_smem);

    dim3 blk(256);

    // QKV projections -> (B,H,S,HD)
    gemm_kernel<<<dim3(ND/64,  NM/64), blk>>>(x, wq, bq, nullptr, q_p, NM, ND, ND, 0, 1);
    gemm_kernel<<<dim3(ND/64,  NM/64), blk>>>(x, wk, bk, nullptr, k_p, NM, ND, ND, 0, 1);
    gemm_kernel<<<dim3(ND/64,  NM/64), blk>>>(x, wv, bv, nullptr, v_p, NM, ND, ND, 0, 1);

    // attention -> (B,S,D)
    attn_kernel<<<dim3(NS/64, NB*NH), blk, attn_smem>>>(q_p, k_p, v_p, attn_p);

    // O projection + residual, then LN1
    gemm_kernel<<<dim3(ND/64,  NM/64), blk>>>(attn_p, wo, bo, x, tmp_p, NM, ND, ND, 0, 0);
    ln_kernel<<<NM, 256>>>(tmp_p, g1, be1, x1_p);

    // FFN
    gemm_kernel<<<dim3(NFF/64, NM/64), blk>>>(x1_p, w1, b1, nullptr, ff_p, NM, NFF, ND, 1, 0);
    gemm_kernel<<<dim3(ND/64,  NM/64), blk>>>(ff_p, w2, b2, x1_p, tmp_p, NM, ND, NFF, 0, 0);
    ln_kernel<<<NM, 256>>>(tmp_p, g2, be2, out);
}